// round 14
// baseline (speedup 1.0000x reference)
#include <cuda_runtime.h>

#define NSP  13824      // 24^3
#define NPAD 17576      // 26^3
#define CCH  64
#define BB   2
#define NBLK_GATE 432   // 13824/32
#define QSC 0.18033688011112042f    // (1/8)*log2(e)
#define FXS 16777216.0f             // 2^24 fixed-point scale

// scratch (zero-initialized at module load; padded borders of g_xk/g_xv stay 0 forever)
__device__ float g_xq[BB*CCH*NSP];
__device__ float g_xk[BB*CCH*NPAD];
__device__ float g_xv[BB*CCH*NPAD];
__device__ float g_attn[BB*CCH*NSP];
__device__ long long g_acc[BB*CCH];          // fixed-point channel sums; gru resets each launch

__device__ __forceinline__ float ex2f_(float x){ float y; asm("ex2.approx.ftz.f32 %0, %1;":"=f"(y):"f"(x)); return y; }
__device__ __forceinline__ float rcpf_(float x){ float y; asm("rcp.approx.ftz.f32 %0, %1;":"=f"(y):"f"(x)); return y; }
__device__ __forceinline__ float sigmf_(float x){ return rcpf_(1.f + ex2f_(-1.44269504f*x)); }

__device__ __forceinline__ unsigned long long ffma2_(unsigned long long a, unsigned long long b, unsigned long long c){
    unsigned long long d; asm("fma.rn.f32x2 %0, %1, %2, %3;" : "=l"(d) : "l"(a), "l"(b), "l"(c)); return d;
}
__device__ __forceinline__ void unpack2_(unsigned long long p, float& a, float& b){
    asm("mov.b64 {%0, %1}, %2;" : "=f"(a), "=f"(b) : "l"(p));
}

// ---------------- Phase A: q/k/v projections, FFMA2 + duplicated-W smem ----------------
// grid (216, 2, 3 passes), 256 threads; tile 64 out x 64 pts; per-thread 4o x 4p.
// smem = xs 16KB + Wdup 32KB = 48KB exactly (no opt-in needed).
__global__ __launch_bounds__(256,4) void proj_kernel(
    const float* __restrict__ x, const float* __restrict__ Wq, const float* __restrict__ bq,
    const float* __restrict__ Wk, const float* __restrict__ Wv)
{
    extern __shared__ float sm[];
    float (*xs)[64] = (float(*)[64])sm;                          // [64][64] floats, 16KB
    unsigned long long* Wd = (unsigned long long*)(sm + 4096);   // [64*64] dup pairs, 32KB
    int n0 = blockIdx.x*64, b = blockIdx.y, pass = blockIdx.z;
    int tid = threadIdx.x;
    const float* W = pass==0?Wq:(pass==1?Wk:Wv);

    const float* xb = x + (size_t)(b*64)*NSP + n0;
    for (int i=tid;i<1024;i+=256){
        int c=i>>4, p4=(i&15)<<2;
        *(float4*)&xs[c][p4] = *(const float4*)(xb + (size_t)c*NSP + p4);
    }
    for (int i=tid;i<4096;i+=256){
        float wv = W[i];
        unsigned long long p; asm("mov.b64 %0, {%1, %1};" : "=l"(p) : "f"(wv));
        Wd[i] = p;
    }
    __syncthreads();

    int og4 = (tid>>4)<<2;       // 16 groups of 4 outputs
    int pbase = (tid&15)<<2;     // 16 groups of 4 points

    unsigned long long acc[4][2];
    #pragma unroll
    for (int i=0;i<4;i++){ acc[i][0]=0ull; acc[i][1]=0ull; }

    #pragma unroll 8
    for (int c=0;c<64;c++){
        ulonglong2 xr = *(const ulonglong2*)&xs[c][pbase];   // LDS.128 -> two packed pairs
        #pragma unroll
        for (int i=0;i<4;i++){
            unsigned long long wp = Wd[(og4+i)*64 + c];      // broadcast LDS.64, pre-duplicated
            acc[i][0] = ffma2_(wp, xr.x, acc[i][0]);
            acc[i][1] = ffma2_(wp, xr.y, acc[i][1]);
        }
    }

    if (pass==0){
        #pragma unroll
        for (int i=0;i<4;i++){
            int o = og4+i;
            float bqv = __ldg(bq+o);
            float v0,v1,v2,v3;
            unpack2_(acc[i][0],v0,v1); unpack2_(acc[i][1],v2,v3);
            float4 s;
            s.x=(v0+bqv)*QSC; s.y=(v1+bqv)*QSC; s.z=(v2+bqv)*QSC; s.w=(v3+bqv)*QSC;
            *(float4*)(g_xq + (size_t)(b*64+o)*NSP + n0 + pbase) = s;
        }
    } else {
        float* dstb = (pass==1)? g_xk : g_xv;
        int n = n0 + pbase;     // 4-aligned; 4-pt group never crosses a 24-row
        int h=n/576, r=n-h*576, d=r/24, w=r-d*24;
        int np0=(h+1)*676+(d+1)*26+(w+1);   // NOT 16B-aligned -> scalar stores only
        #pragma unroll
        for (int i=0;i<4;i++){
            int o = og4+i;
            float v0,v1,v2,v3;
            unpack2_(acc[i][0],v0,v1); unpack2_(acc[i][1],v2,v3);
            float* dst = dstb + (size_t)(b*64+o)*NPAD + np0;
            dst[0]=v0; dst[1]=v1; dst[2]=v2; dst[3]=v3;
        }
    }
}

// ---------------- Phase B: per-channel scalar softmax attention (proven R2 version) ----------------
__global__ __launch_bounds__(256) void attn_kernel(
    const float* __restrict__ bk, const float* __restrict__ bv,
    const float* __restrict__ mk, const float* __restrict__ mv)
{
    int bc = blockIdx.y;              // b*64 + c
    int c  = bc & 63;
    int n  = blockIdx.x*256 + threadIdx.x;
    int h=n/576, r=n-h*576, d=r/24, w=r-d*24;
    int np=(h+1)*676+(d+1)*26+(w+1);
    float qs  = g_xq[bc*NSP+n];       // q * log2e/8
    float bkc = __ldg(bk+c), bvc = __ldg(bv+c);
    float qbk = qs*bkc;
    const float* Kp = g_xk + (size_t)bc*NPAD + np;
    const float* Vp = g_xv + (size_t)bc*NPAD + np;
    float den=0.f, num=0.f, dens=0.f;
    #pragma unroll
    for (int m=0;m<5;m++){
        float e = ex2f_(qs*__ldg(mk+c*5+m));
        den += e;
        num  = fmaf(e, __ldg(mv+c*5+m), num);
    }
    #pragma unroll
    for (int j=0;j<27;j++){
        int dz=j/9, rr=j-dz*9, dy=rr/3, dx=rr-dy*3;
        int off=(dz-1)*676+(dy-1)*26+(dx-1);
        float kv=__ldg(Kp+off), vv=__ldg(Vp+off);
        float e = ex2f_(fmaf(qs,kv,qbk));
        dens += e;
        num   = fmaf(e,vv,num);
    }
    num = fmaf(bvc,dens,num);
    g_attn[bc*NSP+n] = num * rcpf_(den+dens);
}

// ---------------- Phase C: gate + blend + fixed-point channel-sum atomics ----------------
__global__ __launch_bounds__(256) void gate_kernel(
    const float* __restrict__ x, const float* __restrict__ Wg,
    const float* __restrict__ bg, float* __restrict__ out)
{
    __shared__ float xs[64][33];
    __shared__ float as[64][33];
    __shared__ float Wb[64][65];
    __shared__ float ssum[64];
    int b=blockIdx.y, n0=blockIdx.x*32, tid=threadIdx.x;
    if (tid<64) ssum[tid]=0.f;
    for (int i=tid;i<2048;i+=256){
        int cc=i>>5, nl=i&31;
        xs[cc][nl]=x[(b*64+cc)*NSP+n0+nl];
        as[cc][nl]=g_attn[(b*64+cc)*NSP+n0+nl];
    }
    int obase=(tid>>4)<<2, nb=(tid&15)<<1;
    float acc[4][2]={};
    for (int half=0;half<2;half++){
        __syncthreads();
        for (int i=tid;i<4096;i+=256) Wb[i>>6][i&63]=Wg[(i>>6)*128 + half*64 + (i&63)];
        __syncthreads();
        #pragma unroll 4
        for (int cc=0;cc<64;cc++){
            float s0 = half ? as[cc][nb]   : xs[cc][nb];
            float s1 = half ? as[cc][nb+1] : xs[cc][nb+1];
            #pragma unroll
            for (int i=0;i<4;i++){
                float wv=Wb[obase+i][cc];
                acc[i][0]=fmaf(wv,s0,acc[i][0]);
                acc[i][1]=fmaf(wv,s1,acc[i][1]);
            }
        }
    }
    #pragma unroll
    for (int i=0;i<4;i++){
        int o=obase+i;
        float bgo=__ldg(bg+o);
        float lsum=0.f;
        #pragma unroll
        for (int j=0;j<2;j++){
            float g  = sigmf_(acc[i][j]+bgo);
            float ov = g*as[o][nb+j] + (1.f-g)*xs[o][nb+j];
            out[(b*64+o)*NSP + n0+nb+j] = ov;
            lsum += ov;
        }
        atomicAdd(&ssum[o], lsum);
    }
    __syncthreads();
    if (tid<64){
        long long q = (long long)llrintf(ssum[tid]*FXS);   // deterministic integer accumulation
        atomicAdd((unsigned long long*)&g_acc[b*64+tid], (unsigned long long)q);
    }
}

// ---------------- Phase D: GRU memory update (1024 thr; reads fixed-point sums, resets) ----------------
__global__ __launch_bounds__(1024) void gru_kernel(
    const float* __restrict__ prev, const float* __restrict__ Wih, const float* __restrict__ Whh,
    const float* __restrict__ bih, const float* __restrict__ bhh, float* __restrict__ out_mem)
{
    __shared__ float mu[128], pm[128];
    int tid = threadIdx.x;
    if (tid < 128){
        mu[tid] = (float)((double)g_acc[tid] * (1.0/(16777216.0*13824.0)));
        pm[tid] = prev[tid];
    }
    __syncthreads();
    if (tid < 128) g_acc[tid] = 0;            // reset for next graph replay

    int w = tid >> 5, lane = tid & 31;
    #pragma unroll
    for (int rep = 0; rep < 4; rep++){
        int p2 = w + rep*32;          // 0..127
        int b = p2 >> 6, o = p2 & 63;
        float a0=0.f,a1=0.f,a2=0.f,a3=0.f,a4=0.f,a5=0.f;
        #pragma unroll
        for (int half = 0; half < 2; half++){
            int cc = lane + half*32;
            float m  = mu[b*64+cc];
            float pv = pm[b*64+cc];
            a0 = fmaf(__ldg(Wih + o*64        + cc), m,  a0);
            a1 = fmaf(__ldg(Wih + (64+o)*64   + cc), m,  a1);
            a2 = fmaf(__ldg(Wih + (128+o)*64  + cc), m,  a2);
            a3 = fmaf(__ldg(Whh + o*64        + cc), pv, a3);
            a4 = fmaf(__ldg(Whh + (64+o)*64   + cc), pv, a4);
            a5 = fmaf(__ldg(Whh + (128+o)*64  + cc), pv, a5);
        }
        #pragma unroll
        for (int off = 16; off; off >>= 1){
            a0 += __shfl_xor_sync(0xffffffffu, a0, off);
            a1 += __shfl_xor_sync(0xffffffffu, a1, off);
            a2 += __shfl_xor_sync(0xffffffffu, a2, off);
            a3 += __shfl_xor_sync(0xffffffffu, a3, off);
            a4 += __shfl_xor_sync(0xffffffffu, a4, off);
            a5 += __shfl_xor_sync(0xffffffffu, a5, off);
        }
        if (lane == 0){
            float gir = a0 + bih[o],     ghr = a3 + bhh[o];
            float giz = a1 + bih[64+o],  ghz = a4 + bhh[64+o];
            float gin = a2 + bih[128+o], ghn = a5 + bhh[128+o];
            float rg  = 1.f/(1.f+expf(-(gir+ghr)));
            float zg  = 1.f/(1.f+expf(-(giz+ghz)));
            float ng2 = tanhf(gin + rg*ghn);
            out_mem[p2] = (1.f-zg)*ng2 + zg*pm[b*64+o];
        }
    }
}

extern "C" void kernel_launch(void* const* d_in, const int* in_sizes, int n_in,
                              void* d_out, int out_size)
{
    const float* x   = (const float*)d_in[0];
    const float* prev= (const float*)d_in[1];
    const float* Wq  = (const float*)d_in[2];
    const float* bq  = (const float*)d_in[3];
    const float* Wk  = (const float*)d_in[4];
    const float* bk  = (const float*)d_in[5];
    const float* Wv  = (const float*)d_in[6];
    const float* bv  = (const float*)d_in[7];
    const float* mk  = (const float*)d_in[8];
    const float* mv  = (const float*)d_in[9];
    const float* Wg  = (const float*)d_in[10];
    const float* bg  = (const float*)d_in[11];
    const float* Wih = (const float*)d_in[12];
    const float* Whh = (const float*)d_in[13];
    const float* bih = (const float*)d_in[14];
    const float* bhh = (const float*)d_in[15];
    float* out = (float*)d_out;

    const int proj_smem = 49152;   // 16KB xs + 32KB Wdup = 48KB (default limit, no opt-in)
    proj_kernel<<<dim3(216,2,3),256,proj_smem>>>(x,Wq,bq,Wk,Wv);
    attn_kernel<<<dim3(54,128),256>>>(bk,bv,mk,mv);
    gate_kernel<<<dim3(NBLK_GATE,2),256>>>(x,Wg,bg,out);
    gru_kernel<<<1,1024>>>(prev,Wih,Whh,bih,bhh,out + (size_t)BB*CCH*NSP);
}

// round 15
// speedup vs baseline: 1.1025x; 1.1025x over previous
#include <cuda_runtime.h>

#define NSP  13824      // 24^3
#define NPAD 17576      // 26^3
#define CCH  64
#define BB   2
#define NBLK_GATE 432   // 13824/32
#define QSC 0.18033688011112042f    // (1/8)*log2(e)
#define FXS 16777216.0f             // 2^24 fixed-point scale

// scratch (zero-initialized at module load; padded borders of g_xk/g_xv stay 0 forever)
__device__ float g_xq[BB*CCH*NSP];
__device__ float g_xk[BB*CCH*NPAD];
__device__ float g_xv[BB*CCH*NPAD];
__device__ float g_attn[BB*CCH*NSP];
__device__ long long g_acc[BB*CCH];          // fixed-point channel sums; gru resets each launch

__device__ __forceinline__ float ex2f_(float x){ float y; asm("ex2.approx.ftz.f32 %0, %1;":"=f"(y):"f"(x)); return y; }
__device__ __forceinline__ float rcpf_(float x){ float y; asm("rcp.approx.ftz.f32 %0, %1;":"=f"(y):"f"(x)); return y; }
__device__ __forceinline__ float sigmf_(float x){ return rcpf_(1.f + ex2f_(-1.44269504f*x)); }

// ---------------- Phase A: fused q/k/v projections, 384 threads, 64o x 96p tile ----------------
// grid (144, 2); smem = xs 24KB + 3 W matrices 48KB = 72KB (opt-in); 3 blocks/SM -> 36 warps/SM.
// All weights loaded ONCE, one sync, then 3 uninterrupted FFMA pass-loops on the same x tile.
__global__ __launch_bounds__(384,3) void proj_kernel(
    const float* __restrict__ x, const float* __restrict__ Wq, const float* __restrict__ bq,
    const float* __restrict__ Wk, const float* __restrict__ Wv)
{
    extern __shared__ float sm[];
    float (*xs)[96] = (float(*)[96])sm;                    // [64][96], 24KB
    float* Wall = sm + 6144;                               // [3][64][64], 48KB
    int n0 = blockIdx.x*96, b = blockIdx.y, tid = threadIdx.x;

    const float* xb = x + (size_t)(b*64)*NSP + n0;
    for (int i=tid;i<1536;i+=384){
        int c = i/24, p4 = (i - c*24)*4;
        *(float4*)&xs[c][p4] = *(const float4*)(xb + (size_t)c*NSP + p4);
    }
    for (int i=tid;i<4096;i+=384){
        Wall[i]      = Wq[i];
        Wall[4096+i] = Wk[i];
        Wall[8192+i] = Wv[i];
    }
    __syncthreads();

    int og4 = (tid/24)*4;        // 16 groups of 4 outputs
    int pbase = (tid - (tid/24)*24)*4;   // 24 groups of 4 points

    // geometry for padded k/v stores (4-aligned group never crosses a 24-row since 24%4==0)
    int n = n0 + pbase;
    int h=n/576, r=n-h*576, d=r/24, w=r-d*24;
    int np0=(h+1)*676+(d+1)*26+(w+1);   // NOT 16B-aligned -> scalar stores only

    #pragma unroll
    for (int pass=0; pass<3; pass++){
        const float* Wp = Wall + pass*4096;
        float acc[4][4];
        #pragma unroll
        for (int i=0;i<4;i++){ acc[i][0]=0.f; acc[i][1]=0.f; acc[i][2]=0.f; acc[i][3]=0.f; }

        #pragma unroll 8
        for (int c=0;c<64;c++){
            float4 xr = *(const float4*)&xs[c][pbase];
            #pragma unroll
            for (int i=0;i<4;i++){
                float wv = Wp[(og4+i)*64 + c];
                acc[i][0]=fmaf(wv,xr.x,acc[i][0]);
                acc[i][1]=fmaf(wv,xr.y,acc[i][1]);
                acc[i][2]=fmaf(wv,xr.z,acc[i][2]);
                acc[i][3]=fmaf(wv,xr.w,acc[i][3]);
            }
        }

        if (pass==0){
            #pragma unroll
            for (int i=0;i<4;i++){
                int o = og4+i;
                float bqv = __ldg(bq+o);
                float4 s;
                s.x=(acc[i][0]+bqv)*QSC; s.y=(acc[i][1]+bqv)*QSC;
                s.z=(acc[i][2]+bqv)*QSC; s.w=(acc[i][3]+bqv)*QSC;
                *(float4*)(g_xq + (size_t)(b*64+o)*NSP + n0 + pbase) = s;
            }
        } else {
            float* dstb = (pass==1)? g_xk : g_xv;
            #pragma unroll
            for (int i=0;i<4;i++){
                int o = og4+i;
                float* dst = dstb + (size_t)(b*64+o)*NPAD + np0;
                dst[0]=acc[i][0]; dst[1]=acc[i][1]; dst[2]=acc[i][2]; dst[3]=acc[i][3];
            }
        }
    }
}

// ---------------- Phase B: per-channel scalar softmax attention (proven R2 version) ----------------
__global__ __launch_bounds__(256) void attn_kernel(
    const float* __restrict__ bk, const float* __restrict__ bv,
    const float* __restrict__ mk, const float* __restrict__ mv)
{
    int bc = blockIdx.y;              // b*64 + c
    int c  = bc & 63;
    int n  = blockIdx.x*256 + threadIdx.x;
    int h=n/576, r=n-h*576, d=r/24, w=r-d*24;
    int np=(h+1)*676+(d+1)*26+(w+1);
    float qs  = g_xq[bc*NSP+n];       // q * log2e/8
    float bkc = __ldg(bk+c), bvc = __ldg(bv+c);
    float qbk = qs*bkc;
    const float* Kp = g_xk + (size_t)bc*NPAD + np;
    const float* Vp = g_xv + (size_t)bc*NPAD + np;
    float den=0.f, num=0.f, dens=0.f;
    #pragma unroll
    for (int m=0;m<5;m++){
        float e = ex2f_(qs*__ldg(mk+c*5+m));
        den += e;
        num  = fmaf(e, __ldg(mv+c*5+m), num);
    }
    #pragma unroll
    for (int j=0;j<27;j++){
        int dz=j/9, rr=j-dz*9, dy=rr/3, dx=rr-dy*3;
        int off=(dz-1)*676+(dy-1)*26+(dx-1);
        float kv=__ldg(Kp+off), vv=__ldg(Vp+off);
        float e = ex2f_(fmaf(qs,kv,qbk));
        dens += e;
        num   = fmaf(e,vv,num);
    }
    num = fmaf(bvc,dens,num);
    g_attn[bc*NSP+n] = num * rcpf_(den+dens);
}

// ---------------- Phase C: gate + blend + fixed-point channel-sum atomics ----------------
__global__ __launch_bounds__(256) void gate_kernel(
    const float* __restrict__ x, const float* __restrict__ Wg,
    const float* __restrict__ bg, float* __restrict__ out)
{
    __shared__ float xs[64][33];
    __shared__ float as[64][33];
    __shared__ float Wb[64][65];
    __shared__ float ssum[64];
    int b=blockIdx.y, n0=blockIdx.x*32, tid=threadIdx.x;
    if (tid<64) ssum[tid]=0.f;
    for (int i=tid;i<2048;i+=256){
        int cc=i>>5, nl=i&31;
        xs[cc][nl]=x[(b*64+cc)*NSP+n0+nl];
        as[cc][nl]=g_attn[(b*64+cc)*NSP+n0+nl];
    }
    int obase=(tid>>4)<<2, nb=(tid&15)<<1;
    float acc[4][2]={};
    for (int half=0;half<2;half++){
        __syncthreads();
        for (int i=tid;i<4096;i+=256) Wb[i>>6][i&63]=Wg[(i>>6)*128 + half*64 + (i&63)];
        __syncthreads();
        #pragma unroll 4
        for (int cc=0;cc<64;cc++){
            float s0 = half ? as[cc][nb]   : xs[cc][nb];
            float s1 = half ? as[cc][nb+1] : xs[cc][nb+1];
            #pragma unroll
            for (int i=0;i<4;i++){
                float wv=Wb[obase+i][cc];
                acc[i][0]=fmaf(wv,s0,acc[i][0]);
                acc[i][1]=fmaf(wv,s1,acc[i][1]);
            }
        }
    }
    #pragma unroll
    for (int i=0;i<4;i++){
        int o=obase+i;
        float bgo=__ldg(bg+o);
        float lsum=0.f;
        #pragma unroll
        for (int j=0;j<2;j++){
            float g  = sigmf_(acc[i][j]+bgo);
            float ov = g*as[o][nb+j] + (1.f-g)*xs[o][nb+j];
            out[(b*64+o)*NSP + n0+nb+j] = ov;
            lsum += ov;
        }
        atomicAdd(&ssum[o], lsum);
    }
    __syncthreads();
    if (tid<64){
        long long q = (long long)llrintf(ssum[tid]*FXS);   // deterministic integer accumulation
        atomicAdd((unsigned long long*)&g_acc[b*64+tid], (unsigned long long)q);
    }
}

// ---------------- Phase D: GRU memory update (1024 thr; reads fixed-point sums, resets) ----------------
__global__ __launch_bounds__(1024) void gru_kernel(
    const float* __restrict__ prev, const float* __restrict__ Wih, const float* __restrict__ Whh,
    const float* __restrict__ bih, const float* __restrict__ bhh, float* __restrict__ out_mem)
{
    __shared__ float mu[128], pm[128];
    int tid = threadIdx.x;
    if (tid < 128){
        mu[tid] = (float)((double)g_acc[tid] * (1.0/(16777216.0*13824.0)));
        pm[tid] = prev[tid];
    }
    __syncthreads();
    if (tid < 128) g_acc[tid] = 0;            // reset for next graph replay

    int w = tid >> 5, lane = tid & 31;
    #pragma unroll
    for (int rep = 0; rep < 4; rep++){
        int p2 = w + rep*32;          // 0..127
        int b = p2 >> 6, o = p2 & 63;
        float a0=0.f,a1=0.f,a2=0.f,a3=0.f,a4=0.f,a5=0.f;
        #pragma unroll
        for (int half = 0; half < 2; half++){
            int cc = lane + half*32;
            float m  = mu[b*64+cc];
            float pv = pm[b*64+cc];
            a0 = fmaf(__ldg(Wih + o*64        + cc), m,  a0);
            a1 = fmaf(__ldg(Wih + (64+o)*64   + cc), m,  a1);
            a2 = fmaf(__ldg(Wih + (128+o)*64  + cc), m,  a2);
            a3 = fmaf(__ldg(Whh + o*64        + cc), pv, a3);
            a4 = fmaf(__ldg(Whh + (64+o)*64   + cc), pv, a4);
            a5 = fmaf(__ldg(Whh + (128+o)*64  + cc), pv, a5);
        }
        #pragma unroll
        for (int off = 16; off; off >>= 1){
            a0 += __shfl_xor_sync(0xffffffffu, a0, off);
            a1 += __shfl_xor_sync(0xffffffffu, a1, off);
            a2 += __shfl_xor_sync(0xffffffffu, a2, off);
            a3 += __shfl_xor_sync(0xffffffffu, a3, off);
            a4 += __shfl_xor_sync(0xffffffffu, a4, off);
            a5 += __shfl_xor_sync(0xffffffffu, a5, off);
        }
        if (lane == 0){
            float gir = a0 + bih[o],     ghr = a3 + bhh[o];
            float giz = a1 + bih[64+o],  ghz = a4 + bhh[64+o];
            float gin = a2 + bih[128+o], ghn = a5 + bhh[128+o];
            float rg  = 1.f/(1.f+expf(-(gir+ghr)));
            float zg  = 1.f/(1.f+expf(-(giz+ghz)));
            float ng2 = tanhf(gin + rg*ghn);
            out_mem[p2] = (1.f-zg)*ng2 + zg*pm[b*64+o];
        }
    }
}

extern "C" void kernel_launch(void* const* d_in, const int* in_sizes, int n_in,
                              void* d_out, int out_size)
{
    const float* x   = (const float*)d_in[0];
    const float* prev= (const float*)d_in[1];
    const float* Wq  = (const float*)d_in[2];
    const float* bq  = (const float*)d_in[3];
    const float* Wk  = (const float*)d_in[4];
    const float* bk  = (const float*)d_in[5];
    const float* Wv  = (const float*)d_in[6];
    const float* bv  = (const float*)d_in[7];
    const float* mk  = (const float*)d_in[8];
    const float* mv  = (const float*)d_in[9];
    const float* Wg  = (const float*)d_in[10];
    const float* bg  = (const float*)d_in[11];
    const float* Wih = (const float*)d_in[12];
    const float* Whh = (const float*)d_in[13];
    const float* bih = (const float*)d_in[14];
    const float* bhh = (const float*)d_in[15];
    float* out = (float*)d_out;

    const int proj_smem = (6144 + 3*4096) * sizeof(float);   // 72KB
    cudaFuncSetAttribute(proj_kernel, cudaFuncAttributeMaxDynamicSharedMemorySize, proj_smem);

    proj_kernel<<<dim3(144,2),384,proj_smem>>>(x,Wq,bq,Wk,Wv);
    attn_kernel<<<dim3(54,128),256>>>(bk,bv,mk,mv);
    gate_kernel<<<dim3(NBLK_GATE,2),256>>>(x,Wg,bg,out);
    gru_kernel<<<1,1024>>>(prev,Wih,Whh,bih,bhh,out + (size_t)BB*CCH*NSP);
}